// round 15
// baseline (speedup 1.0000x reference)
#include <cuda_runtime.h>
#include <cuda_fp16.h>
#include <cstdint>
#include <math.h>

#define MAIL   8
#define DMEM   128
#define DCAT   256
#define NPB    8
#define ROWS   64
#define NTHR   256

#define AH 264             // A / QK row stride in halves
#define MHH 136            // MH row stride in halves
#define QHS 72             // QH / attn-tile row stride in halves

// ---- smem byte offsets ----
#define OFF_NODE 0
#define OFF_TIME 32
#define OFF_BV   64                      // 128 f32 -> 576
#define OFF_ATT  576                     // 128 f32 -> 1088
#define OFF_ATT2 1088                    // 128 f32 -> 1600
#define OFF_DT   1600                    // 64 f32 -> 1856
#define OFF_QB   1856                    // 16 f32 -> 1920
#define OFF_MEM  1920                    // 8x128 f32 -> 6016
#define OFF_OUT  6016                    // 8x128 f32 -> 10112
#define OFF_MH   10112                   // 16x136 h -> 14464 (rows 8-15 zero)
#define OFF_QH   14464                   // 16x72 h -> 16768 (attn tiles overlay)
#define OFF_QK   16768                   // 16x264 h -> 25216
#define OFF_A    25216                   // 64x264 h -> 59008
#define SMEM_TOTAL 59008

__device__ __align__(16) uint32_t g_QKf[16384];
__device__ __align__(16) uint32_t g_VF[16384];
__device__ __align__(16) uint32_t g_WqF[8192];
__device__ __align__(16) uint32_t g_MlF[8192];

__device__ __forceinline__ uint32_t smem_u32(const void* p) {
    uint32_t a;
    asm("{ .reg .u64 t; cvta.to.shared.u64 t, %1; cvt.u32.u64 %0, t; }"
        : "=r"(a) : "l"(p));
    return a;
}
__device__ __forceinline__ void ldsm4(uint32_t addr, uint32_t& r0, uint32_t& r1,
                                      uint32_t& r2, uint32_t& r3) {
    asm volatile("ldmatrix.sync.aligned.m8n8.x4.shared.b16 {%0,%1,%2,%3}, [%4];"
                 : "=r"(r0), "=r"(r1), "=r"(r2), "=r"(r3) : "r"(addr));
}
__device__ __forceinline__ void ldsm4t(uint32_t addr, uint32_t& r0, uint32_t& r1,
                                       uint32_t& r2, uint32_t& r3) {
    asm volatile("ldmatrix.sync.aligned.m8n8.x4.trans.shared.b16 {%0,%1,%2,%3}, [%4];"
                 : "=r"(r0), "=r"(r1), "=r"(r2), "=r"(r3) : "r"(addr));
}
__device__ __forceinline__ void mma16816(float* c, uint32_t a0, uint32_t a1,
                                         uint32_t a2, uint32_t a3,
                                         uint32_t b0, uint32_t b1) {
    asm volatile("mma.sync.aligned.m16n8k16.row.col.f32.f16.f16.f32 "
                 "{%0,%1,%2,%3},{%4,%5,%6,%7},{%8,%9},{%0,%1,%2,%3};"
                 : "+f"(c[0]), "+f"(c[1]), "+f"(c[2]), "+f"(c[3])
                 : "r"(a0), "r"(a1), "r"(a2), "r"(a3), "r"(b0), "r"(b1));
}
__device__ __forceinline__ uint32_t pack_h2(float x, float y) {
    __half2 h = __halves2half2(__float2half_rn(x), __float2half_rn(y));
    return *(uint32_t*)&h;
}

__global__ void prep_weights(const float* __restrict__ wq,
                             const float* __restrict__ wk,
                             const float* __restrict__ wv,
                             const float* __restrict__ mlp) {
    int i = blockIdx.x * 256 + threadIdx.x;           // 0..65535
    if (i < 16384) {
        int breg = i & 1;
        int lane = (i >> 1) & 31;
        int nt   = (i >> 6) & 7;
        int ks   = (i >> 9) & 3;
        int w    = (i >> 11) & 7;
        int h  = w >> 2;
        int nc = (w & 3) * 64;
        int kr = ks * 16 + breg * 8 + (lane & 3) * 2;
        int kp = nc + nt * 8 + (lane >> 2);
        g_QKf[i] = pack_h2(wk[(h * 64 + kr) * 256 + kp],
                           wk[(h * 64 + kr + 1) * 256 + kp]);
    } else if (i < 32768) {
        int jj = i - 16384;
        int breg = jj & 1, l = (jj >> 1) & 31;
        int nt = (jj >> 6) & 1, ks = (jj >> 7) & 15, w = (jj >> 11) & 7;
        int h = w >> 2, j = w & 3;
        int col = h * 64 + j * 16 + nt * 8 + (l >> 2);
        int k0  = ks * 16 + breg * 8 + (l & 3) * 2;
        g_VF[jj] = pack_h2(wv[col * 256 + k0], wv[col * 256 + k0 + 1]);
    } else if (i < 49152) {
        int j = i - 32768;
        const float* W = (j < 8192) ? wq : mlp;
        int jj = j & 8191;
        int breg = jj & 1, l = (jj >> 1) & 31;
        int nt = (jj >> 6) & 1, ks = (jj >> 7) & 7, w = (jj >> 10) & 7;
        int col = w * 16 + nt * 8 + (l >> 2);
        int k0  = ks * 16 + breg * 8 + (l & 3) * 2;
        uint32_t v = pack_h2(W[col * 128 + k0], W[col * 128 + k0 + 1]);
        if (j < 8192) g_WqF[jj] = v; else g_MlF[jj] = v;
    }
}

__global__ __launch_bounds__(NTHR, 3)
void attn_mma_kernel(
    const int*   __restrict__ nodes,
    const float* __restrict__ times,
    const float* __restrict__ mem,
    const float* __restrict__ mail,
    const float* __restrict__ mail_time,
    const float* __restrict__ time_w,
    const float* __restrict__ time_b,
    const float* __restrict__ wq_b,
    const float* __restrict__ wk_b,
    const float* __restrict__ wv_b,
    const float* __restrict__ mlp_b,
    const float* __restrict__ ln_g,
    const float* __restrict__ ln_b,
    float*       __restrict__ out,
    int size)
{
    extern __shared__ __align__(1024) char smem[];
    const uint32_t sb = smem_u32(smem);
    const int tid = threadIdx.x, warp = tid >> 5, lane = tid & 31;
    const int base = blockIdx.x * NPB;

    int*   s_node = (int*)(smem + OFF_NODE);
    float* s_time = (float*)(smem + OFF_TIME);
    float* s_bv   = (float*)(smem + OFF_BV);
    float* s_att  = (float*)(smem + OFF_ATT);
    float* s_att2 = (float*)(smem + OFF_ATT2);
    float* s_dt   = (float*)(smem + OFF_DT);
    float* s_qb   = (float*)(smem + OFF_QB);
    float* s_memf = (float*)(smem + OFF_MEM);
    float* s_out  = (float*)(smem + OFF_OUT);

    if (tid < NPB) {
        int g = base + tid; if (g >= size) g = size - 1;
        s_node[tid] = nodes[g];
        s_time[tid] = times[g];
    }
    if (tid >= 32 && tid < 48) s_qb[tid - 32] = 0.f;
    if (tid >= 128) s_bv[tid - 128] = wv_b[tid - 128];
    __syncthreads();

    if (tid < ROWS) {
        int n = tid >> 3, slot = tid & 7;
        s_dt[tid] = s_time[n] - __ldg(mail_time + (size_t)s_node[n] * MAIL + slot);
    }

    // gather mem rows (fp32) + hi fp16 into MH rows 0-7
    {
        int n = tid >> 5, c4 = (tid & 31) * 4;
        float4 v = *(const float4*)(mem + (size_t)s_node[n] * DMEM + c4);
        ((float4*)s_memf)[tid] = v;
        uint2 hv = { pack_h2(v.x, v.y), pack_h2(v.z, v.w) };
        *(uint2*)(smem + OFF_MH + (uint32_t)(n * MHH + c4) * 2) = hv;
    }
    // zero MH rows 8-15
    for (int i = tid; i < 8 * 68; i += NTHR) {
        int r = 8 + i / 68, c = (i % 68) * 2;
        *(uint32_t*)(smem + OFF_MH + (uint32_t)(r * MHH + c) * 2) = 0u;
    }

    // mail half of A (fp16)
    {
        const int c4 = (tid & 31) * 4;
        #pragma unroll
        for (int t = 0; t < 8; t++) {
            int r = (tid >> 5) + t * 8;
            int n = r >> 3, slot = r & 7;
            float4 mv = *(const float4*)(mail + ((size_t)s_node[n] * MAIL + slot) * 128 + c4);
            uint2 hv = { pack_h2(mv.x, mv.y), pack_h2(mv.z, mv.w) };
            *(uint2*)(smem + OFF_A + ((size_t)r * AH + c4) * 2) = hv;
        }
    }
    __syncthreads();

    // time-encode half of A
    {
        const int j = (tid & 63) * 2;
        const float tw0 = __ldg(time_w + j), tw1 = __ldg(time_w + j + 1);
        const float tb0 = __ldg(time_b + j), tb1 = __ldg(time_b + j + 1);
        #pragma unroll
        for (int t = 0; t < 16; t++) {
            int r = (tid >> 6) + t * 4;
            float dt = s_dt[r];
            float v0 = __cosf(fmaf(dt, tw0, tb0));
            float v1 = __cosf(fmaf(dt, tw1, tb1));
            *(uint32_t*)(smem + OFF_A + ((size_t)r * AH + 128 + j) * 2) = pack_h2(v0, v1);
        }
    }

    const int g8 = lane >> 3, lr = lane & 7;
    const uint32_t mrow = lr + ((g8 & 1) << 3);
    const uint32_t mko  = (uint32_t)((g8 >> 1) << 3);
    const uint32_t mHa  = sb + OFF_MH + (mrow * MHH + mko) * 2;
    const int r4 = lane >> 2, cpos = 2 * (lane & 3);

    // ---- Q via MMA: warp w -> cols [w*16, w*16+16); 8 real rows ----
    {
        float qa0[4] = {0.f, 0.f, 0.f, 0.f}, qa1[4] = {0.f, 0.f, 0.f, 0.f};
        const uint2* wfq = (const uint2*)g_WqF + (uint32_t)warp * 512 + lane;
        #pragma unroll
        for (int ks = 0; ks < 8; ks++) {
            uint2 bh0 = __ldg(wfq + ks * 64);
            uint2 bh1 = __ldg(wfq + ks * 64 + 32);
            uint32_t ah0, ah1, ah2, ah3;
            ldsm4(mHa + (uint32_t)ks * 32, ah0, ah1, ah2, ah3);
            mma16816(qa0, ah0, ah1, ah2, ah3, bh0.x, bh0.y);
            mma16816(qa1, ah0, ah1, ah2, ah3, bh1.x, bh1.y);
        }
        int col = warp * 16 + cpos;
        int h = warp >> 2;
        int cl = (warp & 3) * 16 + cpos;
        float b0 = __ldg(wq_b + col),     b1 = __ldg(wq_b + col + 1);
        float b8 = __ldg(wq_b + col + 8), b9 = __ldg(wq_b + col + 9);
        float q00 = qa0[0] + b0, q01 = qa0[1] + b1;
        float q10 = qa1[0] + b8, q11 = qa1[1] + b9;
        uint32_t rowA = (uint32_t)(h * 8 + r4) * QHS * 2;
        *(uint32_t*)(smem + OFF_QH + rowA + (uint32_t)cl * 2)       = pack_h2(q00, q01);
        *(uint32_t*)(smem + OFF_QH + rowA + (uint32_t)(cl + 8) * 2) = pack_h2(q10, q11);
        float k0 = __ldg(wk_b + col),     k1 = __ldg(wk_b + col + 1);
        float k8 = __ldg(wk_b + col + 8), k9 = __ldg(wk_b + col + 9);
        atomicAdd(&s_qb[r4 * 2 + h], q00 * k0 + q01 * k1 + q10 * k8 + q11 * k9);
    }
    __syncthreads();

    // ---- Qk GEMM: warp w (h=w>>2, kappa chunk (w&3)*64), A = QH rows h*8.. ----
    {
        const int h = warp >> 2, nc = (warp & 3) * 64;
        const uint32_t aQ = sb + OFF_QH + (((uint32_t)(h * 8) + mrow) * QHS + mko) * 2;
        float acc[8][4];
        #pragma unroll
        for (int t = 0; t < 8; t++)
            #pragma unroll
            for (int u = 0; u < 4; u++) acc[t][u] = 0.f;
        const uint2* wf = (const uint2*)g_QKf + (uint32_t)warp * 1024 + lane;
        #pragma unroll
        for (int ks = 0; ks < 4; ks++) {
            uint32_t a0, a1, a2, a3;
            ldsm4(aQ + (uint32_t)ks * 32, a0, a1, a2, a3);
            #pragma unroll
            for (int nt = 0; nt < 8; nt++) {
                uint2 b = __ldg(wf + (ks * 8 + nt) * 32);
                mma16816(acc[nt], a0, a1, a2, a3, b.x, b.y);
            }
        }
        #pragma unroll
        for (int nt = 0; nt < 8; nt++) {
            int k0 = nc + nt * 8 + cpos;
            *(uint32_t*)(smem + OFF_QK + ((uint32_t)(r4 * 2 + h) * AH + k0) * 2) =
                pack_h2(acc[nt][0], acc[nt][1]);
        }
    }
    __syncthreads();                                 // QK ready; QH dead

    // ---- logits GEMM (split-K): warp w -> rows (w&3)*16, k-half (w>>2)*128 ----
    {
        // parallel zero of attn tile (16 rows x 32 words)
        #pragma unroll
        for (int z = 0; z < 2; z++) {
            int idx = tid + z * NTHR;                // 0..511
            int row = idx >> 5, wrd = idx & 31;
            *(uint32_t*)(smem + OFF_QH + (uint32_t)row * QHS * 2 + (uint32_t)wrd * 4) = 0u;
        }
        const int kh = warp >> 2, rw = (warp & 3) * 16;
        const uint32_t aL = sb + OFF_A +
            (((uint32_t)rw + mrow) * AH + (uint32_t)(kh * 128) + mko) * 2;
        const uint32_t bL0 = sb + OFF_QK +
            (((uint32_t)(lane & 7)) * AH + (uint32_t)(kh * 128) + ((uint32_t)(lane >> 3) << 3)) * 2;
        const uint32_t bL1 = bL0 + 8 * AH * 2;
        float acc0[4] = {0.f, 0.f, 0.f, 0.f};
        float acc1[4] = {0.f, 0.f, 0.f, 0.f};
        #pragma unroll
        for (int kp = 0; kp < 4; kp++) {
            uint32_t b0, b1, b2, b3, c0, c1, c2, c3;
            ldsm4(bL0 + (uint32_t)kp * 64, b0, b1, b2, b3);
            ldsm4(bL1 + (uint32_t)kp * 64, c0, c1, c2, c3);
            uint32_t a0, a1, a2, a3;
            ldsm4(aL + (uint32_t)kp * 64, a0, a1, a2, a3);
            mma16816(acc0, a0, a1, a2, a3, b0, b1);
            mma16816(acc1, a0, a1, a2, a3, c0, c1);
            ldsm4(aL + (uint32_t)kp * 64 + 32, a0, a1, a2, a3);
            mma16816(acc0, a0, a1, a2, a3, b2, b3);
            mma16816(acc1, a0, a1, a2, a3, c2, c3);
        }
        float* dst = kh ? s_att2 : s_att;
        #pragma unroll
        for (int u = 0; u < 4; u++) {
            int grow = rw + (u >> 1) * 8 + r4;
            int node = grow >> 3, slot = grow & 7;
            int c0 = cpos + (u & 1);                 // acc0 col (0..7 range x2)
            float v0 = acc0[u], v1 = acc1[u];
            if (c0 == 2 * node)     dst[(node * 8 + slot) * 2 + 0] = v0;
            if (c0 == 2 * node + 1) dst[(node * 8 + slot) * 2 + 1] = v0;
            int c1 = c0 + 8;
            if (c1 == 2 * node)     dst[(node * 8 + slot) * 2 + 0] = v1;
            if (c1 == 2 * node + 1) dst[(node * 8 + slot) * 2 + 1] = v1;
        }
    }
    __syncthreads();

    // ---- softmax (sum split-K partials + qb + leaky), write 4 tile words ----
    if (tid < 16) {
        int n = tid >> 1, h = tid & 1;
        float lg[MAIL];
        float qb = s_qb[n * 2 + h];
        float mx = -1e30f;
        #pragma unroll
        for (int s = 0; s < MAIL; s++) {
            float v = s_att[(n * 8 + s) * 2 + h] + s_att2[(n * 8 + s) * 2 + h] + qb;
            v = (v >= 0.f) ? v : 0.2f * v;
            lg[s] = v;
            mx = fmaxf(mx, v);
        }
        float ex[MAIL], sum = 0.f;
        #pragma unroll
        for (int s = 0; s < MAIL; s++) { ex[s] = __expf(lg[s] - mx); sum += ex[s]; }
        float inv = 1.f / sum;
        uint32_t rowB = (uint32_t)OFF_QH + (uint32_t)(h * 8 + n) * QHS * 2
                      + (uint32_t)n * 16;
        #pragma unroll
        for (int w = 0; w < 4; w++) {
            int s2 = w * 2;
            *(uint32_t*)(smem + rowB + (uint32_t)w * 4) =
                pack_h2(ex[s2] * inv, ex[s2 + 1] * inv);
        }
    }
    __syncthreads();

    // ---- contraction via MMA: weighted[h*8+n, c] = attnTile @ Mcat; warp w -> cols w*32 ----
    {
        const int cchunk = warp * 32;
        const uint32_t aT = sb + OFF_QH +
            (((uint32_t)(lane & 15)) * QHS + ((uint32_t)(lane >> 4) << 3)) * 2;
        const uint32_t bT = sb + OFF_A +
            (((uint32_t)(lane & 15)) * AH + (uint32_t)cchunk + ((uint32_t)(lane >> 4) << 3)) * 2;
        float acc[4][4];
        #pragma unroll
        for (int q = 0; q < 4; q++)
            #pragma unroll
            for (int u = 0; u < 4; u++) acc[q][u] = 0.f;
        #pragma unroll
        for (int ks = 0; ks < 4; ks++) {
            uint32_t a0, a1, a2, a3;
            ldsm4(aT + (uint32_t)ks * 32, a0, a1, a2, a3);
            #pragma unroll
            for (int nn2 = 0; nn2 < 2; nn2++) {
                uint32_t r0, r1, r2, r3;
                ldsm4t(bT + ((uint32_t)(ks * 16) * AH + (uint32_t)(nn2 * 16)) * 2,
                       r0, r1, r2, r3);
                mma16816(acc[nn2 * 2],     a0, a1, a2, a3, r0, r1);
                mma16816(acc[nn2 * 2 + 1], a0, a1, a2, a3, r2, r3);
            }
        }
        // store rows r4 and r4+8 (all 16 real), own column chunk
        #pragma unroll
        for (int nn = 0; nn < 4; nn++) {
            uint32_t c2 = (uint32_t)(cchunk + nn * 8 + cpos) * 2;
            *(uint32_t*)(smem + OFF_A + (uint32_t)r4 * AH * 2 + c2) =
                pack_h2(acc[nn][0], acc[nn][1]);
            *(uint32_t*)(smem + OFF_A + (uint32_t)(r4 + 8) * AH * 2 + c2) =
                pack_h2(acc[nn][2], acc[nn][3]);
        }
    }
    __syncthreads();

    // ---- V GEMM: warp w -> head h=w>>2, cols (w&3)*16; A rows h*8.. ----
    {
        const int h = warp >> 2, j = warp & 3;
        const uint32_t aHi = sb + OFF_A + (((uint32_t)(h * 8) + mrow) * AH + mko) * 2;
        float qa0[4] = {0.f, 0.f, 0.f, 0.f}, qa1[4] = {0.f, 0.f, 0.f, 0.f};
        const uint2* wfv = (const uint2*)g_VF + (uint32_t)warp * 1024 + lane;
        uint2 b0 = __ldg(wfv);
        uint2 b1 = __ldg(wfv + 32);
        #pragma unroll
        for (int ks = 0; ks < 16; ks++) {
            uint2 nb0, nb1;
            if (ks < 15) {
                nb0 = __ldg(wfv + (ks + 1) * 64);
                nb1 = __ldg(wfv + (ks + 1) * 64 + 32);
            }
            uint32_t h0, h1, h2, h3;
            ldsm4(aHi + (uint32_t)ks * 32, h0, h1, h2, h3);
            mma16816(qa0, h0, h1, h2, h3, b0.x, b0.y);
            mma16816(qa1, h0, h1, h2, h3, b1.x, b1.y);
            b0 = nb0; b1 = nb1;
        }
        int col = h * 64 + j * 16 + cpos;
        int node = r4;                               // rows 0-7 real
        s_out[node * 128 + col]     = qa0[0] + s_bv[col]     + s_memf[node * 128 + col];
        s_out[node * 128 + col + 1] = qa0[1] + s_bv[col + 1] + s_memf[node * 128 + col + 1];
        s_out[node * 128 + col + 8] = qa1[0] + s_bv[col + 8] + s_memf[node * 128 + col + 8];
        s_out[node * 128 + col + 9] = qa1[1] + s_bv[col + 9] + s_memf[node * 128 + col + 9];
    }
    __syncthreads();

    // ---- LayerNorm: warp n -> node n; writes hi fp16 into MH row n ----
    {
        int n = warp;
        float4 x4 = ((float4*)(s_out + n * 128))[lane];
        float sum = x4.x + x4.y + x4.z + x4.w;
        float sq  = fmaf(x4.x, x4.x, fmaf(x4.y, x4.y, fmaf(x4.z, x4.z, x4.w * x4.w)));
        #pragma unroll
        for (int off = 16; off; off >>= 1) {
            sum += __shfl_xor_sync(0xffffffffu, sum, off);
            sq  += __shfl_xor_sync(0xffffffffu, sq, off);
        }
        float mu = sum * (1.f / 128.f);
        float rstd = rsqrtf(sq * (1.f / 128.f) - mu * mu + 1e-5f);
        float o[4] = {x4.x, x4.y, x4.z, x4.w};
        float y[4];
        #pragma unroll
        for (int u = 0; u < 4; u++) {
            int cc = lane * 4 + u;
            y[u] = (o[u] - mu) * rstd * __ldg(ln_g + cc) + __ldg(ln_b + cc);
        }
        uint2 hv = { pack_h2(y[0], y[1]), pack_h2(y[2], y[3]) };
        *(uint2*)(smem + OFF_MH + (uint32_t)(n * MHH + lane * 4) * 2) = hv;
    }
    __syncthreads();

    // ---- MLP via MMA + ReLU + store (rows 0-7 real) ----
    {
        float qa0[4] = {0.f, 0.f, 0.f, 0.f}, qa1[4] = {0.f, 0.f, 0.f, 0.f};
        const uint2* wfm = (const uint2*)g_MlF + (uint32_t)warp * 512 + lane;
        #pragma unroll
        for (int ks = 0; ks < 8; ks++) {
            uint2 bh0 = __ldg(wfm + ks * 64);
            uint2 bh1 = __ldg(wfm + ks * 64 + 32);
            uint32_t ah0, ah1, ah2, ah3;
            ldsm4(mHa + (uint32_t)ks * 32, ah0, ah1, ah2, ah3);
            mma16816(qa0, ah0, ah1, ah2, ah3, bh0.x, bh0.y);
            mma16816(qa1, ah0, ah1, ah2, ah3, bh1.x, bh1.y);
        }
        int col = warp * 16 + cpos;
        float b0 = __ldg(mlp_b + col),     b1 = __ldg(mlp_b + col + 1);
        float b8 = __ldg(mlp_b + col + 8), b9 = __ldg(mlp_b + col + 9);
        int g0 = base + r4;
        if (g0 < size) {
            float2 v0 = { fmaxf(qa0[0] + b0, 0.f), fmaxf(qa0[1] + b1, 0.f) };
            float2 v1 = { fmaxf(qa1[0] + b8, 0.f), fmaxf(qa1[1] + b9, 0.f) };
            *(float2*)(out + (size_t)g0 * 128 + col)     = v0;
            *(float2*)(out + (size_t)g0 * 128 + col + 8) = v1;
        }
    }
}

extern "C" void kernel_launch(void* const* d_in, const int* in_sizes, int n_in,
                              void* d_out, int out_size) {
    const int*   nodes     = (const int*)  d_in[0];
    const float* times     = (const float*)d_in[1];
    const float* mem       = (const float*)d_in[2];
    const float* mail      = (const float*)d_in[3];
    const float* mail_time = (const float*)d_in[4];
    const float* time_w    = (const float*)d_in[5];
    const float* time_b    = (const float*)d_in[6];
    const float* wq_w      = (const float*)d_in[7];
    const float* wq_b      = (const float*)d_in[8];
    const float* wk_w      = (const float*)d_in[9];
    const float* wk_b      = (const float*)d_in[10];
    const float* wv_w      = (const float*)d_in[11];
    const float* wv_b      = (const float*)d_in[12];
    const float* mlp_w     = (const float*)d_in[13];
    const float* mlp_b     = (const float*)d_in[14];
    const float* ln_g      = (const float*)d_in[15];
    const float* ln_b      = (const float*)d_in[16];
    int size = in_sizes[0];

    cudaFuncSetAttribute(attn_mma_kernel,
                         cudaFuncAttributeMaxDynamicSharedMemorySize, SMEM_TOTAL);

    prep_weights<<<256, 256>>>(wq_w, wk_w, wv_w, mlp_w);

    int nblk = (size + NPB - 1) / NPB;
    attn_mma_kernel<<<nblk, NTHR, SMEM_TOTAL>>>(
        nodes, times, mem, mail, mail_time, time_w, time_b,
        wq_b, wk_b, wv_b, mlp_b, ln_g, ln_b,
        (float*)d_out, size);
}

// round 16
// speedup vs baseline: 1.1646x; 1.1646x over previous
#include <cuda_runtime.h>
#include <cuda_fp16.h>
#include <cstdint>
#include <math.h>

#define MAIL   8
#define DMEM   128
#define DCAT   256
#define NPB    16
#define ROWS   128
#define NTHR   256

#define AH 264             // A / QK row stride in halves
#define MHH 136            // MH row stride in halves
#define QHS 72             // QH / attn-tile row stride in halves

// ---- smem byte offsets ----
#define OFF_NODE 0
#define OFF_TIME 64
#define OFF_BV   128
#define OFF_ATT  640
#define OFF_DT   1664
#define OFF_QB   2176
#define OFF_MEM  2304                    // 16x128 f32 -> 10496
#define OFF_OUT  10496                   // 16x128 f32 -> 18688
#define OFF_MH   18688                   // 16x136 halves -> 23040
#define OFF_QH   23040                   // 2x16x72 halves -> 27648 (attn tiles overlay)
#define OFF_QK   27648                   // 32x264 halves -> 44544
#define OFF_A    44544                   // 128x264 halves -> 112128
#define SMEM_TOTAL 112128

__device__ __align__(16) uint32_t g_QKf[16384];
__device__ __align__(16) uint32_t g_VF[16384];
__device__ __align__(16) uint32_t g_WqF[8192];
__device__ __align__(16) uint32_t g_MlF[8192];

__device__ __forceinline__ uint32_t smem_u32(const void* p) {
    uint32_t a;
    asm("{ .reg .u64 t; cvta.to.shared.u64 t, %1; cvt.u32.u64 %0, t; }"
        : "=r"(a) : "l"(p));
    return a;
}
__device__ __forceinline__ void ldsm4(uint32_t addr, uint32_t& r0, uint32_t& r1,
                                      uint32_t& r2, uint32_t& r3) {
    asm volatile("ldmatrix.sync.aligned.m8n8.x4.shared.b16 {%0,%1,%2,%3}, [%4];"
                 : "=r"(r0), "=r"(r1), "=r"(r2), "=r"(r3) : "r"(addr));
}
__device__ __forceinline__ void ldsm4t(uint32_t addr, uint32_t& r0, uint32_t& r1,
                                       uint32_t& r2, uint32_t& r3) {
    asm volatile("ldmatrix.sync.aligned.m8n8.x4.trans.shared.b16 {%0,%1,%2,%3}, [%4];"
                 : "=r"(r0), "=r"(r1), "=r"(r2), "=r"(r3) : "r"(addr));
}
__device__ __forceinline__ void mma16816(float* c, uint32_t a0, uint32_t a1,
                                         uint32_t a2, uint32_t a3,
                                         uint32_t b0, uint32_t b1) {
    asm volatile("mma.sync.aligned.m16n8k16.row.col.f32.f16.f16.f32 "
                 "{%0,%1,%2,%3},{%4,%5,%6,%7},{%8,%9},{%0,%1,%2,%3};"
                 : "+f"(c[0]), "+f"(c[1]), "+f"(c[2]), "+f"(c[3])
                 : "r"(a0), "r"(a1), "r"(a2), "r"(a3), "r"(b0), "r"(b1));
}
__device__ __forceinline__ uint32_t pack_h2(float x, float y) {
    __half2 h = __halves2half2(__float2half_rn(x), __float2half_rn(y));
    return *(uint32_t*)&h;
}
__device__ __forceinline__ float fast_cos(float x) {
    // |x| < 0.2: 1 - x^2/2 (abs err < 7e-6, far below fp16 rounding);
    // branch is warp-uniform for the high-j feature warps -> MUFU skipped.
    if (fabsf(x) < 0.2f) return fmaf(-0.5f * x, x, 1.f);
    return __cosf(x);
}

__global__ void prep_weights(const float* __restrict__ wq,
                             const float* __restrict__ wk,
                             const float* __restrict__ wv,
                             const float* __restrict__ mlp) {
    int i = blockIdx.x * 256 + threadIdx.x;           // 0..65535
    if (i < 16384) {
        int breg = i & 1;
        int lane = (i >> 1) & 31;
        int nt   = (i >> 6) & 7;
        int ks   = (i >> 9) & 3;
        int w    = (i >> 11) & 7;
        int h  = w >> 2;
        int nc = (w & 3) * 64;
        int kr = ks * 16 + breg * 8 + (lane & 3) * 2;
        int kp = nc + nt * 8 + (lane >> 2);
        g_QKf[i] = pack_h2(wk[(h * 64 + kr) * 256 + kp],
                           wk[(h * 64 + kr + 1) * 256 + kp]);
    } else if (i < 32768) {
        int jj = i - 16384;
        int breg = jj & 1, l = (jj >> 1) & 31;
        int nt = (jj >> 6) & 1, ks = (jj >> 7) & 15, w = (jj >> 11) & 7;
        int h = w >> 2, j = w & 3;
        int col = h * 64 + j * 16 + nt * 8 + (l >> 2);
        int k0  = ks * 16 + breg * 8 + (l & 3) * 2;
        g_VF[jj] = pack_h2(wv[col * 256 + k0], wv[col * 256 + k0 + 1]);
    } else if (i < 49152) {
        int j = i - 32768;
        const float* W = (j < 8192) ? wq : mlp;
        int jj = j & 8191;
        int breg = jj & 1, l = (jj >> 1) & 31;
        int nt = (jj >> 6) & 1, ks = (jj >> 7) & 7, w = (jj >> 10) & 7;
        int col = w * 16 + nt * 8 + (l >> 2);
        int k0  = ks * 16 + breg * 8 + (l & 3) * 2;
        uint32_t v = pack_h2(W[col * 128 + k0], W[col * 128 + k0 + 1]);
        if (j < 8192) g_WqF[jj] = v; else g_MlF[jj] = v;
    }
}

__global__ __launch_bounds__(NTHR, 2)
void attn_mma_kernel(
    const int*   __restrict__ nodes,
    const float* __restrict__ times,
    const float* __restrict__ mem,
    const float* __restrict__ mail,
    const float* __restrict__ mail_time,
    const float* __restrict__ time_w,
    const float* __restrict__ time_b,
    const float* __restrict__ wq_b,
    const float* __restrict__ wk_b,
    const float* __restrict__ wv_b,
    const float* __restrict__ mlp_b,
    const float* __restrict__ ln_g,
    const float* __restrict__ ln_b,
    float*       __restrict__ out,
    int size)
{
    extern __shared__ __align__(1024) char smem[];
    const uint32_t sb = smem_u32(smem);
    const int tid = threadIdx.x, warp = tid >> 5, lane = tid & 31;
    const int base = blockIdx.x * NPB;

    int*   s_node = (int*)(smem + OFF_NODE);
    float* s_time = (float*)(smem + OFF_TIME);
    float* s_bv   = (float*)(smem + OFF_BV);
    float* s_att  = (float*)(smem + OFF_ATT);
    float* s_dt   = (float*)(smem + OFF_DT);
    float* s_qb   = (float*)(smem + OFF_QB);
    float* s_memf = (float*)(smem + OFF_MEM);
    float* s_out  = (float*)(smem + OFF_OUT);

    if (tid < NPB) {
        int g = base + tid; if (g >= size) g = size - 1;
        s_node[tid] = nodes[g];
        s_time[tid] = times[g];
    }
    if (tid >= 32 && tid < 64) s_qb[tid - 32] = 0.f;
    if (tid >= 128) s_bv[tid - 128] = wv_b[tid - 128];
    __syncthreads();

    if (tid < ROWS) {
        int n = tid >> 3, slot = tid & 7;
        s_dt[tid] = s_time[n] - __ldg(mail_time + (size_t)s_node[n] * MAIL + slot);
    }

    // gather mem rows (fp32) + hi fp16 copy into MH
    #pragma unroll
    for (int t = 0; t < 2; t++) {
        int idx = tid + t * NTHR;
        int n = idx >> 5, c4 = (idx & 31) * 4;
        float4 v = *(const float4*)(mem + (size_t)s_node[n] * DMEM + c4);
        ((float4*)s_memf)[idx] = v;
        uint2 hv = { pack_h2(v.x, v.y), pack_h2(v.z, v.w) };
        *(uint2*)(smem + OFF_MH + (uint32_t)(n * MHH + c4) * 2) = hv;
    }

    // mail half of A (fp16)
    {
        const int c4 = (tid & 31) * 4;
        #pragma unroll
        for (int t = 0; t < 16; t++) {
            int r = (tid >> 5) + t * 8;
            int n = r >> 3, slot = r & 7;
            float4 mv = *(const float4*)(mail + ((size_t)s_node[n] * MAIL + slot) * 128 + c4);
            uint2 hv = { pack_h2(mv.x, mv.y), pack_h2(mv.z, mv.w) };
            *(uint2*)(smem + OFF_A + ((size_t)r * AH + c4) * 2) = hv;
        }
    }
    __syncthreads();

    // time-encode half of A (poly fast-path for small |x|)
    {
        const int j = (tid & 63) * 2;
        const float tw0 = __ldg(time_w + j), tw1 = __ldg(time_w + j + 1);
        const float tb0 = __ldg(time_b + j), tb1 = __ldg(time_b + j + 1);
        #pragma unroll
        for (int t = 0; t < 32; t++) {
            int r = (tid >> 6) + t * 4;
            float dt = s_dt[r];
            float v0 = fast_cos(fmaf(dt, tw0, tb0));
            float v1 = fast_cos(fmaf(dt, tw1, tb1));
            *(uint32_t*)(smem + OFF_A + ((size_t)r * AH + 128 + j) * 2) = pack_h2(v0, v1);
        }
    }

    const int g8 = lane >> 3, lr = lane & 7;
    const uint32_t mrow = lr + ((g8 & 1) << 3);
    const uint32_t mko  = (uint32_t)((g8 >> 1) << 3);
    const uint32_t mHa  = sb + OFF_MH + (mrow * MHH + mko) * 2;
    const int r4 = lane >> 2, cpos = 2 * (lane & 3);

    // ---- Q via MMA: warp w -> cols [w*16, w*16+16); write QH fp16 + qb atomics ----
    {
        float qa0[4] = {0.f, 0.f, 0.f, 0.f}, qa1[4] = {0.f, 0.f, 0.f, 0.f};
        const uint2* wfq = (const uint2*)g_WqF + (uint32_t)warp * 512 + lane;
        uint2 p0 = __ldg(wfq);
        uint2 p1 = __ldg(wfq + 32);
        #pragma unroll
        for (int ks = 0; ks < 8; ks++) {
            uint2 n0, n1;
            if (ks < 7) { n0 = __ldg(wfq + (ks + 1) * 64); n1 = __ldg(wfq + (ks + 1) * 64 + 32); }
            uint32_t ah0, ah1, ah2, ah3;
            ldsm4(mHa + (uint32_t)ks * 32, ah0, ah1, ah2, ah3);
            mma16816(qa0, ah0, ah1, ah2, ah3, p0.x, p0.y);
            mma16816(qa1, ah0, ah1, ah2, ah3, p1.x, p1.y);
            p0 = n0; p1 = n1;
        }
        int col = warp * 16 + cpos;
        int h = warp >> 2;
        int cl = (warp & 3) * 16 + cpos;
        float b0 = __ldg(wq_b + col),     b1 = __ldg(wq_b + col + 1);
        float b8 = __ldg(wq_b + col + 8), b9 = __ldg(wq_b + col + 9);
        float q00 = qa0[0] + b0, q01 = qa0[1] + b1;
        float q02 = qa0[2] + b0, q03 = qa0[3] + b1;
        float q10 = qa1[0] + b8, q11 = qa1[1] + b9;
        float q12 = qa1[2] + b8, q13 = qa1[3] + b9;
        uint32_t rowA = (uint32_t)(h * 16 + r4) * QHS * 2;
        uint32_t rowB = (uint32_t)(h * 16 + r4 + 8) * QHS * 2;
        *(uint32_t*)(smem + OFF_QH + rowA + (uint32_t)cl * 2)       = pack_h2(q00, q01);
        *(uint32_t*)(smem + OFF_QH + rowB + (uint32_t)cl * 2)       = pack_h2(q02, q03);
        *(uint32_t*)(smem + OFF_QH + rowA + (uint32_t)(cl + 8) * 2) = pack_h2(q10, q11);
        *(uint32_t*)(smem + OFF_QH + rowB + (uint32_t)(cl + 8) * 2) = pack_h2(q12, q13);
        float k0 = __ldg(wk_b + col),     k1 = __ldg(wk_b + col + 1);
        float k8 = __ldg(wk_b + col + 8), k9 = __ldg(wk_b + col + 9);
        float cA = q00 * k0 + q01 * k1 + q10 * k8 + q11 * k9;
        float cB = q02 * k0 + q03 * k1 + q12 * k8 + q13 * k9;
        atomicAdd(&s_qb[r4 * 2 + h], cA);
        atomicAdd(&s_qb[(r4 + 8) * 2 + h], cB);
    }
    __syncthreads();

    // ---- Qk GEMM: Qk[n*2+h, kappa] = Q_h[n,:] @ Wk_h^T ----
    {
        const int h = warp >> 2, nc = (warp & 3) * 64;
        const uint32_t aQ = sb + OFF_QH + (((uint32_t)(h * 16) + mrow) * QHS + mko) * 2;
        float acc[8][4];
        #pragma unroll
        for (int t = 0; t < 8; t++)
            #pragma unroll
            for (int u = 0; u < 4; u++) acc[t][u] = 0.f;
        const uint2* wf = (const uint2*)g_QKf + (uint32_t)warp * 1024 + lane;
        #pragma unroll
        for (int ks = 0; ks < 4; ks++) {
            uint32_t a0, a1, a2, a3;
            ldsm4(aQ + (uint32_t)ks * 32, a0, a1, a2, a3);
            #pragma unroll
            for (int nt = 0; nt < 8; nt++) {
                uint2 b = __ldg(wf + (ks * 8 + nt) * 32);
                mma16816(acc[nt], a0, a1, a2, a3, b.x, b.y);
            }
        }
        #pragma unroll
        for (int nt = 0; nt < 8; nt++) {
            int k0 = nc + nt * 8 + cpos;
            *(uint32_t*)(smem + OFF_QK + ((uint32_t)(r4 * 2 + h) * AH + k0) * 2) =
                pack_h2(acc[nt][0], acc[nt][1]);
            *(uint32_t*)(smem + OFF_QK + ((uint32_t)((r4 + 8) * 2 + h) * AH + k0) * 2) =
                pack_h2(acc[nt][2], acc[nt][3]);
        }
    }
    __syncthreads();                                 // QK ready; QH now dead

    // ---- logits GEMM (+ parallel zero of attn tiles in dead QH region) ----
    {
        #pragma unroll
        for (int z = 0; z < 4; z++) {
            int idx = tid + z * NTHR;                // 0..1023
            int row = idx >> 5, wrd = idx & 31;
            *(uint32_t*)(smem + OFF_QH + (uint32_t)row * QHS * 2 + (uint32_t)wrd * 4) = 0u;
        }
        const int t = warp >> 1;
        const uint32_t aL = sb + OFF_A + (((uint32_t)(warp * 16) + mrow) * AH + mko) * 2;
        const uint32_t bL = sb + OFF_QK +
            (((uint32_t)(8 * t + (lane & 7))) * AH + ((uint32_t)(lane >> 3) << 3)) * 2;
        float acc[4] = {0.f, 0.f, 0.f, 0.f};
        #pragma unroll
        for (int kp = 0; kp < 8; kp++) {
            uint32_t b0, b1, b2, b3;
            ldsm4(bL + (uint32_t)kp * 64, b0, b1, b2, b3);
            uint32_t a0, a1, a2, a3;
            ldsm4(aL + (uint32_t)kp * 64, a0, a1, a2, a3);
            mma16816(acc, a0, a1, a2, a3, b0, b1);
            ldsm4(aL + (uint32_t)kp * 64 + 32, a0, a1, a2, a3);
            mma16816(acc, a0, a1, a2, a3, b2, b3);
        }
        #pragma unroll
        for (int u = 0; u < 4; u++) {
            int row = (u >> 1) * 8 + r4;
            int colg = 8 * t + cpos + (u & 1);
            int n = colg >> 1, h2 = colg & 1;
            if (n == 2 * warp + (row >> 3)) {
                float v = acc[u] + s_qb[n * 2 + h2];
                v = (v >= 0.f) ? v : 0.2f * v;
                s_att[(n * 8 + (row & 7)) * 2 + h2] = v;
            }
        }
    }
    __syncthreads();

    // ---- softmax: writes ONLY its 4 nonzero tile words ----
    if (tid < 32) {
        int n = tid >> 1, h = tid & 1;
        float mx = -1e30f;
        #pragma unroll
        for (int s = 0; s < MAIL; s++) mx = fmaxf(mx, s_att[(n * 8 + s) * 2 + h]);
        float ex[MAIL], sum = 0.f;
        #pragma unroll
        for (int s = 0; s < MAIL; s++) { ex[s] = __expf(s_att[(n * 8 + s) * 2 + h] - mx); sum += ex[s]; }
        float inv = 1.f / sum;
        int t = n >> 3, rloc = (n & 7) * 2 + h;
        uint32_t rowB = (uint32_t)OFF_QH + (uint32_t)(t * 16 + rloc) * QHS * 2
                      + (uint32_t)(n & 7) * 16;
        #pragma unroll
        for (int w = 0; w < 4; w++) {
            int s2 = w * 2;
            *(uint32_t*)(smem + rowB + (uint32_t)w * 4) =
                pack_h2(ex[s2] * inv, ex[s2 + 1] * inv);
        }
    }
    __syncthreads();

    // ---- contraction via MMA: weighted[h*16+n, c] = attnTile @ Mcat ----
    {
        const int t = warp >> 2, cchunk = (warp & 3) * 64;
        const uint32_t aT = sb + OFF_QH +
            (((uint32_t)(t * 16 + (lane & 15))) * QHS + ((uint32_t)(lane >> 4) << 3)) * 2;
        const uint32_t bT = sb + OFF_A +
            (((uint32_t)(64 * t + (lane & 15))) * AH + (uint32_t)cchunk + ((uint32_t)(lane >> 4) << 3)) * 2;
        float acc[8][4];
        #pragma unroll
        for (int q = 0; q < 8; q++)
            #pragma unroll
            for (int u = 0; u < 4; u++) acc[q][u] = 0.f;
        #pragma unroll
        for (int ks = 0; ks < 4; ks++) {
            uint32_t a0, a1, a2, a3;
            ldsm4(aT + (uint32_t)ks * 32, a0, a1, a2, a3);
            #pragma unroll
            for (int nn2 = 0; nn2 < 4; nn2++) {
                uint32_t r0, r1, r2, r3;
                ldsm4t(bT + ((uint32_t)(ks * 16) * AH + (uint32_t)(nn2 * 16)) * 2,
                       r0, r1, r2, r3);
                mma16816(acc[nn2 * 2],     a0, a1, a2, a3, r0, r1);
                mma16816(acc[nn2 * 2 + 1], a0, a1, a2, a3, r2, r3);
            }
        }
        int n0 = 8 * t + (r4 >> 1), hh = r4 & 1;
        uint32_t ro0 = (uint32_t)(hh * 16 + n0) * AH * 2;
        uint32_t ro1 = (uint32_t)(hh * 16 + n0 + 4) * AH * 2;
        #pragma unroll
        for (int nn = 0; nn < 8; nn++) {
            uint32_t c2 = (uint32_t)(cchunk + nn * 8 + cpos) * 2;
            *(uint32_t*)(smem + OFF_A + ro0 + c2) = pack_h2(acc[nn][0], acc[nn][1]);
            *(uint32_t*)(smem + OFF_A + ro1 + c2) = pack_h2(acc[nn][2], acc[nn][3]);
        }
    }
    __syncthreads();

    // ---- V GEMM on contracted rows (software-pipelined B prefetch) ----
    {
        const int h = warp >> 2, j = warp & 3;
        const uint32_t aHi = sb + OFF_A + (((uint32_t)(h * 16) + mrow) * AH + mko) * 2;
        float qa0[4] = {0.f, 0.f, 0.f, 0.f}, qa1[4] = {0.f, 0.f, 0.f, 0.f};
        const uint2* wfv = (const uint2*)g_VF + (uint32_t)warp * 1024 + lane;
        uint2 b0 = __ldg(wfv);
        uint2 b1 = __ldg(wfv + 32);
        #pragma unroll
        for (int ks = 0; ks < 16; ks++) {
            uint2 nb0, nb1;
            if (ks < 15) {
                nb0 = __ldg(wfv + (ks + 1) * 64);
                nb1 = __ldg(wfv + (ks + 1) * 64 + 32);
            }
            uint32_t h0, h1, h2, h3;
            ldsm4(aHi + (uint32_t)ks * 32, h0, h1, h2, h3);
            mma16816(qa0, h0, h1, h2, h3, b0.x, b0.y);
            mma16816(qa1, h0, h1, h2, h3, b1.x, b1.y);
            b0 = nb0; b1 = nb1;
        }
        int col = h * 64 + j * 16 + cpos;
        #pragma unroll
        for (int half = 0; half < 2; half++) {
            int node = r4 + half * 8;
            float v0 = (half ? qa0[2] : qa0[0]) + s_bv[col]     + s_memf[node * 128 + col];
            float v1 = (half ? qa0[3] : qa0[1]) + s_bv[col + 1] + s_memf[node * 128 + col + 1];
            float v8 = (half ? qa1[2] : qa1[0]) + s_bv[col + 8] + s_memf[node * 128 + col + 8];
            float v9 = (half ? qa1[3] : qa1[1]) + s_bv[col + 9] + s_memf[node * 128 + col + 9];
            s_out[node * 128 + col]     = v0;
            s_out[node * 128 + col + 1] = v1;
            s_out[node * 128 + col + 8] = v8;
            s_out[node * 128 + col + 9] = v9;
        }
    }
    __syncthreads();

    // ---- LayerNorm: warp handles 2 nodes; writes hi fp16 into MH ----
    #pragma unroll
    for (int t = 0; t < 2; t++) {
        int n = warp * 2 + t;
        float4 x4 = ((float4*)(s_out + n * 128))[lane];
        float sum = x4.x + x4.y + x4.z + x4.w;
        float sq  = fmaf(x4.x, x4.x, fmaf(x4.y, x4.y, fmaf(x4.z, x4.z, x4.w * x4.w)));
        #pragma unroll
        for (int off = 16; off; off >>= 1) {
            sum += __shfl_xor_sync(0xffffffffu, sum, off);
            sq  += __shfl_xor_sync(0xffffffffu, sq, off);
        }
        float mu = sum * (1.f / 128.f);
        float rstd = rsqrtf(sq * (1.f / 128.f) - mu * mu + 1e-5f);
        float o[4] = {x4.x, x4.y, x4.z, x4.w};
        float y[4];
        #pragma unroll
        for (int u = 0; u < 4; u++) {
            int cc = lane * 4 + u;
            y[u] = (o[u] - mu) * rstd * __ldg(ln_g + cc) + __ldg(ln_b + cc);
        }
        uint2 hv = { pack_h2(y[0], y[1]), pack_h2(y[2], y[3]) };
        *(uint2*)(smem + OFF_MH + (uint32_t)(n * MHH + lane * 4) * 2) = hv;
    }
    __syncthreads();

    // ---- MLP via MMA + ReLU + store (pipelined B prefetch) ----
    {
        float qa0[4] = {0.f, 0.f, 0.f, 0.f}, qa1[4] = {0.f, 0.f, 0.f, 0.f};
        const uint2* wfm = (const uint2*)g_MlF + (uint32_t)warp * 512 + lane;
        uint2 p0 = __ldg(wfm);
        uint2 p1 = __ldg(wfm + 32);
        #pragma unroll
        for (int ks = 0; ks < 8; ks++) {
            uint2 n0, n1;
            if (ks < 7) { n0 = __ldg(wfm + (ks + 1) * 64); n1 = __ldg(wfm + (ks + 1) * 64 + 32); }
            uint32_t ah0, ah1, ah2, ah3;
            ldsm4(mHa + (uint32_t)ks * 32, ah0, ah1, ah2, ah3);
            mma16816(qa0, ah0, ah1, ah2, ah3, p0.x, p0.y);
            mma16816(qa1, ah0, ah1, ah2, ah3, p1.x, p1.y);
            p0 = n0; p1 = n1;
        }
        int col = warp * 16 + cpos;
        float b0 = __ldg(mlp_b + col),     b1 = __ldg(mlp_b + col + 1);
        float b8 = __ldg(mlp_b + col + 8), b9 = __ldg(mlp_b + col + 9);
        int g0 = base + r4, g1 = base + r4 + 8;
        if (g0 < size) {
            float2 v0 = { fmaxf(qa0[0] + b0, 0.f), fmaxf(qa0[1] + b1, 0.f) };
            float2 v1 = { fmaxf(qa1[0] + b8, 0.f), fmaxf(qa1[1] + b9, 0.f) };
            *(float2*)(out + (size_t)g0 * 128 + col)     = v0;
            *(float2*)(out + (size_t)g0 * 128 + col + 8) = v1;
        }
        if (g1 < size) {
            float2 v0 = { fmaxf(qa0[2] + b0, 0.f), fmaxf(qa0[3] + b1, 0.f) };
            float2 v1 = { fmaxf(qa1[2] + b8, 0.f), fmaxf(qa1[3] + b9, 0.f) };
            *(float2*)(out + (size_t)g1 * 128 + col)     = v0;
            *(float2*)(out + (size_t)g1 * 128 + col + 8) = v1;
        }
    }
}

extern "C" void kernel_launch(void* const* d_in, const int* in_sizes, int n_in,
                              void* d_out, int out_size) {
    const int*   nodes     = (const int*)  d_in[0];
    const float* times     = (const float*)d_in[1];
    const float* mem       = (const float*)d_in[2];
    const float* mail      = (const float*)d_in[3];
    const float* mail_time = (const float*)d_in[4];
    const float* time_w    = (const float*)d_in[5];
    const float* time_b    = (const float*)d_in[6];
    const float* wq_w      = (const float*)d_in[7];
    const float* wq_b      = (const float*)d_in[8];
    const float* wk_w      = (const float*)d_in[9];
    const float* wk_b      = (const float*)d_in[10];
    const float* wv_w      = (const float*)d_in[11];
    const float* wv_b      = (const float*)d_in[12];
    const float* mlp_w     = (const float*)d_in[13];
    const float* mlp_b     = (const float*)d_in[14];
    const float* ln_g      = (const float*)d_in[15];
    const float* ln_b      = (const float*)d_in[16];
    int size = in_sizes[0];

    cudaFuncSetAttribute(attn_mma_kernel,
                         cudaFuncAttributeMaxDynamicSharedMemorySize, SMEM_TOTAL);

    prep_weights<<<256, 256>>>(wq_w, wk_w, wv_w, mlp_w);

    int nblk = (size + NPB - 1) / NPB;
    attn_mma_kernel<<<nblk, NTHR, SMEM_TOTAL>>>(
        nodes, times, mem, mail, mail_time, time_w, time_b,
        wq_b, wk_b, wv_b, mlp_b, ln_g, ln_b,
        (float*)d_out, size);
}